// round 16
// baseline (speedup 1.0000x reference)
#include <cuda_runtime.h>
#include <cuda_bf16.h>
#include <cuda_fp16.h>

#define N_NODES 50000
#define D 16
#define H 64
#define RECW 96            // words per node record (384B): P half2[32] Q half2[32] x[16] rsd pad
#define TILE 256
#define BLOCK 256

__device__ float g_acc[N_NODES * D];   // zeroed at module load; out_kernel restores zeros
__device__ float g_deg[N_NODES];
__device__ float g_rec[N_NODES * RECW];

__device__ __forceinline__ void red_add_v4(float* addr, float a, float b, float c, float d) {
    asm volatile("red.global.add.v4.f32 [%0], {%1, %2, %3, %4};"
                 :: "l"(addr), "f"(a), "f"(b), "f"(c), "f"(d) : "memory");
}
__device__ __forceinline__ float relu_(float v) { return fmaxf(v, 0.0f); }
__device__ __forceinline__ unsigned h2_bits(__half2 h) {
    return *reinterpret_cast<unsigned*>(&h);
}
__device__ __forceinline__ float2 h2_to_f2(unsigned raw) {
    __half2 h = *reinterpret_cast<__half2*>(&raw);
    return __half22float2(h);
}
__device__ __forceinline__ void ldmatrix_x4(unsigned& a0, unsigned& a1, unsigned& a2, unsigned& a3,
                                            unsigned addr) {
    asm volatile("ldmatrix.sync.aligned.m8n8.x4.shared.b16 {%0,%1,%2,%3}, [%4];"
                 : "=r"(a0), "=r"(a1), "=r"(a2), "=r"(a3) : "r"(addr));
}
__device__ __forceinline__ void ldmatrix_x2(unsigned& b0, unsigned& b1, unsigned addr) {
    asm volatile("ldmatrix.sync.aligned.m8n8.x2.shared.b16 {%0,%1}, [%2];"
                 : "=r"(b0), "=r"(b1) : "r"(addr));
}
__device__ __forceinline__ void mma_16816(float& c0, float& c1, float& c2, float& c3,
                                          unsigned a0, unsigned a1, unsigned a2, unsigned a3,
                                          unsigned b0, unsigned b1) {
    asm volatile("mma.sync.aligned.m16n8k16.row.col.f32.f16.f16.f32 "
                 "{%0,%1,%2,%3}, {%4,%5,%6,%7}, {%8,%9}, {%0,%1,%2,%3};"
                 : "+f"(c0), "+f"(c1), "+f"(c2), "+f"(c3)
                 : "r"(a0), "r"(a1), "r"(a2), "r"(a3), "r"(b0), "r"(b1));
}

__global__ void deg_kernel(const int* __restrict__ ei, int E) {
    int e = blockIdx.x * blockDim.x + threadIdx.x;
    if (e >= E) return;
    atomicAdd(&g_deg[ei[e]], 1.0f);
    atomicAdd(&g_deg[ei[E + e]], 1.0f);
}

// Per node: P = W1a@x, Q = W1b@x stored half2; x fp32; rsd = 1/sqrt(max(deg,1e-5))
__global__ __launch_bounds__(256)
void node_kernel(const float* __restrict__ x, const float* __restrict__ W1, int n_nodes)
{
    __shared__ float w1s[H * 32];
    for (int i = threadIdx.x; i < H * 32; i += blockDim.x) w1s[i] = W1[i];
    __syncthreads();

    int n = blockIdx.x * blockDim.x + threadIdx.x;
    if (n >= n_nodes) return;

    float xv[D];
    const float4* px = (const float4*)(x + (size_t)n * D);
#pragma unroll
    for (int q = 0; q < 4; q++) {
        float4 v4 = px[q];
        xv[4 * q + 0] = v4.x; xv[4 * q + 1] = v4.y;
        xv[4 * q + 2] = v4.z; xv[4 * q + 3] = v4.w;
    }

    float* rec = &g_rec[(size_t)n * RECW];
    unsigned* recu = (unsigned*)rec;
#pragma unroll 4
    for (int jg = 0; jg < H / 4; jg++) {
        float p[4], qv[4];
#pragma unroll
        for (int jj = 0; jj < 4; jj++) {
            const float* w = &w1s[(jg * 4 + jj) * 32];
            float p0 = 0.f, p1 = 0.f, q0 = 0.f, q1 = 0.f;
#pragma unroll
            for (int k = 0; k < D; k += 2) {
                p0 = fmaf(w[k],          xv[k],     p0);
                p1 = fmaf(w[k + 1],      xv[k + 1], p1);
                q0 = fmaf(w[16 + k],     xv[k],     q0);
                q1 = fmaf(w[16 + k + 1], xv[k + 1], q1);
            }
            p[jj] = p0 + p1;
            qv[jj] = q0 + q1;
        }
        recu[2 * jg + 0]      = h2_bits(__floats2half2_rn(p[0], p[1]));
        recu[2 * jg + 1]      = h2_bits(__floats2half2_rn(p[2], p[3]));
        recu[32 + 2 * jg + 0] = h2_bits(__floats2half2_rn(qv[0], qv[1]));
        recu[32 + 2 * jg + 1] = h2_bits(__floats2half2_rn(qv[2], qv[3]));
    }
#pragma unroll
    for (int q = 0; q < 4; q++)
        *(float4*)(rec + 64 + 4 * q) = px[q];
    rec[80] = rsqrtf(fmaxf(g_deg[n], 1e-5f));
}

// SMEM (u32 words):
//   hA   [512 rows * 32]  rows 0..255 hu / x-s, rows 256..511 hw / x-d (XOR chunk swizzle)
//   w2h  fp16 [16 * 72]   (576 u32)
//   b1f[64], b2s[16], rsdS[256], rsdD[256], eis[256], eid[256]
#define SMEM_WORDS (16384 + 576 + 64 + 16 + 256 + 256 + 256 + 256)

__global__ __launch_bounds__(BLOCK, 3)
void edge_kernel(const int* __restrict__ ei,
                 const float* __restrict__ b1, const float* __restrict__ W2f,
                 const float* __restrict__ b2, int E)
{
    extern __shared__ unsigned smemu[];
    unsigned* hA  = smemu;                         // 16384
    __half*  w2h  = (__half*)(smemu + 16384);      // 576 u32
    float*   b1f  = (float*)(smemu + 16384 + 576); // 64
    float*   b2s  = b1f + 64;                      // 16
    float*   rsdS = b2s + 16;                      // 256
    float*   rsdD = rsdS + 256;                    // 256
    int*     eis  = (int*)(rsdD + 256);            // 256
    int*     eid  = eis + 256;                     // 256
    float*   hAf  = (float*)hA;

    const float* __restrict__ rec = g_rec;

    int tid = threadIdx.x, lane = tid & 31, w = tid >> 5;
    int e0 = blockIdx.x * TILE;

    // ---- init loads ----
    for (int i = tid; i < D * H; i += BLOCK) {       // W2f row-major [16][64]
        int r = i >> 6, c = i & 63;
        w2h[r * 72 + c] = __float2half(W2f[i]);
    }
    if (tid < H) b1f[tid] = b1[tid];
    if (tid < D) b2s[tid] = b2[tid];
    {
        int eg = e0 + tid; if (eg >= E) eg = E - 1;
        eis[tid] = ei[eg];
        eid[tid] = ei[E + eg];
    }
    __syncthreads();

    // ---- phase 1: coalesced fp16 PQ gather -> hu/hw rows (64 half each, swizzled) ----
    {
        int half_ = lane >> 4, cl = lane & 15;
        int sub = cl & 7;                 // 16B chunk (8 hidden units)
        int isHW = cl >> 3;               // 0: hu = P_s+Q_d ; 1: hw = P_d+Q_s
        float bb[8];
#pragma unroll
        for (int k = 0; k < 8; k++) bb[k] = b1f[8 * sub + k];
#pragma unroll 4
        for (int it = 0; it < TILE / 16; it++) {
            int eL = it * 16 + (w << 1) + half_;
            int s = eis[eL], d = eid[eL];
            const unsigned* rn1 = (const unsigned*)(rec + (size_t)(isHW ? d : s) * RECW);
            const unsigned* rn2 = (const unsigned*)(rec + (size_t)(isHW ? s : d) * RECW);
            uint4 v1 = *(const uint4*)(rn1 + 4 * sub);        // P piece (8 half)
            uint4 v2 = *(const uint4*)(rn2 + 32 + 4 * sub);   // Q piece (8 half)
            uint4 o;
            { float2 a = h2_to_f2(v1.x), b = h2_to_f2(v2.x);
              o.x = h2_bits(__floats2half2_rn(relu_(a.x + b.x + bb[0]), relu_(a.y + b.y + bb[1]))); }
            { float2 a = h2_to_f2(v1.y), b = h2_to_f2(v2.y);
              o.y = h2_bits(__floats2half2_rn(relu_(a.x + b.x + bb[2]), relu_(a.y + b.y + bb[3]))); }
            { float2 a = h2_to_f2(v1.z), b = h2_to_f2(v2.z);
              o.z = h2_bits(__floats2half2_rn(relu_(a.x + b.x + bb[4]), relu_(a.y + b.y + bb[5]))); }
            { float2 a = h2_to_f2(v1.w), b = h2_to_f2(v2.w);
              o.w = h2_bits(__floats2half2_rn(relu_(a.x + b.x + bb[6]), relu_(a.y + b.y + bb[7]))); }
            int row = isHW ? (256 + eL) : eL;
            *(uint4*)(hA + row * 32 + ((sub ^ (row & 7)) << 2)) = o;
        }
    }
    __syncthreads();

    // ---- MMA phase (warp-local: warp w owns edges [32w, 32w+32)) ----
    unsigned hbase = (unsigned)__cvta_generic_to_shared(hA);
    unsigned wbase = (unsigned)__cvta_generic_to_shared(w2h);

    unsigned bf[2][4][2];
    {
        int l15 = lane & 15;
#pragma unroll
        for (int n = 0; n < 2; n++)
#pragma unroll
            for (int kt = 0; kt < 4; kt++) {
                unsigned addr = wbase + (8 * n + (l15 & 7)) * 144 + kt * 32 + ((l15 >> 3) << 4);
                ldmatrix_x2(bf[n][kt][0], bf[n][kt][1], addr);
            }
    }

    int rl = lane >> 2, cc = 2 * (lane & 3);
#pragma unroll
    for (int m = 0; m < 4; m++) {
        int rowbase = (m < 2) ? (32 * w + 16 * m) : (256 + 32 * w + 16 * (m - 2));
        float c0[4] = {0.f, 0.f, 0.f, 0.f};
        float c1[4] = {0.f, 0.f, 0.f, 0.f};
#pragma unroll
        for (int kt = 0; kt < 4; kt++) {
            int r = rowbase + (lane & 15);
            unsigned chunk = 2 * kt + (lane >> 4);
            unsigned addr = hbase + r * 128 + ((chunk ^ (unsigned)(r & 7)) << 4);
            unsigned a0, a1, a2, a3;
            ldmatrix_x4(a0, a1, a2, a3, addr);
            mma_16816(c0[0], c0[1], c0[2], c0[3], a0, a1, a2, a3, bf[0][kt][0], bf[0][kt][1]);
            mma_16816(c1[0], c1[1], c1[2], c1[3], a0, a1, a2, a3, bf[1][kt][0], bf[1][kt][1]);
        }
        // D -> smem rows, chunks 0..3 (fu / fw, 16 fp32)
#pragma unroll
        for (int hh = 0; hh < 2; hh++) {
            int R = rowbase + rl + 8 * hh;
            int sw = R & 7;
            {
                int fidx = cc;                       // n=0 cols 0..7
                float* p = hAf + R * 32 + (((fidx >> 2) ^ sw) << 2) + (fidx & 3);
                *(float2*)p = make_float2(hh ? c0[2] : c0[0], hh ? c0[3] : c0[1]);
            }
            {
                int fidx = 8 + cc;                   // n=1 cols 8..15
                float* p = hAf + R * 32 + (((fidx >> 2) ^ sw) << 2) + (fidx & 3);
                *(float2*)p = make_float2(hh ? c1[2] : c1[0], hh ? c1[3] : c1[1]);
            }
        }
    }

    // ---- x + rsd staging (warp-local, quad-cooperative) into chunks 4..7 ----
    {
        int eq = lane >> 2, t = lane & 3;
#pragma unroll
        for (int it = 0; it < 4; it++) {
            int eL = 32 * w + it * 8 + eq;
            int s = eis[eL], d = eid[eL];
            const float* rs = rec + (size_t)s * RECW;
            const float* rd = rec + (size_t)d * RECW;
            float4 a = *(const float4*)(rs + 64 + 4 * t);
            float4 b = *(const float4*)(rd + 64 + 4 * t);
            int Ru = eL, Rw = 256 + eL;
            int ch = 4 + t;
            *(float4*)(hAf + Ru * 32 + ((ch ^ (Ru & 7)) << 2)) = a;   // xs
            *(float4*)(hAf + Rw * 32 + ((ch ^ (Rw & 7)) << 2)) = b;   // xd
            if (t == 0) rsdS[eL] = rs[80];
            if (t == 1) rsdD[eL] = rd[80];
        }
    }
    __syncwarp();

    // ---- epilogue: thread-per-edge dots + messages (all reads warp-local) ----
    {
        int e = tid;
        int sw = e & 7;
        float fu[16], fw[16], xs[16], xd[16];
#pragma unroll
        for (int q = 0; q < 4; q++) {
            float4 a  = *(const float4*)(hAf + e * 32 + ((q ^ sw) << 2));
            float4 xA = *(const float4*)(hAf + e * 32 + (((q + 4) ^ sw) << 2));
            float4 b  = *(const float4*)(hAf + (256 + e) * 32 + ((q ^ sw) << 2));
            float4 xB = *(const float4*)(hAf + (256 + e) * 32 + (((q + 4) ^ sw) << 2));
            fu[4*q+0] = a.x;  fu[4*q+1] = a.y;  fu[4*q+2] = a.z;  fu[4*q+3] = a.w;
            xs[4*q+0] = xA.x; xs[4*q+1] = xA.y; xs[4*q+2] = xA.z; xs[4*q+3] = xA.w;
            fw[4*q+0] = b.x;  fw[4*q+1] = b.y;  fw[4*q+2] = b.z;  fw[4*q+3] = b.w;
            xd[4*q+0] = xB.x; xd[4*q+1] = xB.y; xd[4*q+2] = xB.z; xd[4*q+3] = xB.w;
        }
#pragma unroll
        for (int i = 0; i < 16; i++) {
            float b2i = b2s[i];
            fu[i] += b2i;
            fw[i] += b2i;
        }
        float coef = rsdS[e] * rsdD[e];

        float n2u = 0.f, n2w = 0.f, puw = 0.f, pu_xd = 0.f, pw_xd = 0.f, pu_xs = 0.f, pw_xs = 0.f;
#pragma unroll
        for (int i = 0; i < 16; i++) {
            n2u   = fmaf(fu[i], fu[i], n2u);
            n2w   = fmaf(fw[i], fw[i], n2w);
            puw   = fmaf(fu[i], fw[i], puw);
            pu_xd = fmaf(fu[i], xd[i], pu_xd);
            pw_xd = fmaf(fw[i], xd[i], pw_xd);
            pu_xs = fmaf(fu[i], xs[i], pu_xs);
            pw_xs = fmaf(fw[i], xs[i], pw_xs);
        }
        float invu = 1.0f / fmaxf(sqrtf(n2u), 1e-12f);
        float invw = 1.0f / fmaxf(sqrtf(n2w), 1e-12f);
        float uw   = puw   * invu * invw;
        float u_xd = pu_xd * invu;
        float w_xd = pw_xd * invw;
        float u_xs = pu_xs * invu;
        float w_xs = pw_xs * invw;

        // F_s = I-2uu^T, F_d = I-2ww^T, L = -F_s^T F_d ; coefficients act on raw fu/fw
        float cu_s = (-2.0f * u_xd + 4.0f * uw * w_xd) * invu;
        float cw_s = (-2.0f * w_xd) * invw;
        float cu_d = (-2.0f * u_xs) * invu;
        float cw_d = (-2.0f * w_xs + 4.0f * uw * u_xs) * invw;

#pragma unroll
        for (int q = 0; q < 4; q++) {
            float4 m;
            m.x = -coef * (xd[4*q+0] + cu_s * fu[4*q+0] + cw_s * fw[4*q+0]);
            m.y = -coef * (xd[4*q+1] + cu_s * fu[4*q+1] + cw_s * fw[4*q+1]);
            m.z = -coef * (xd[4*q+2] + cu_s * fu[4*q+2] + cw_s * fw[4*q+2]);
            m.w = -coef * (xd[4*q+3] + cu_s * fu[4*q+3] + cw_s * fw[4*q+3]);
            *(float4*)(hAf + e * 32 + ((q ^ sw) << 2)) = m;                 // ms
        }
#pragma unroll
        for (int q = 0; q < 4; q++) {
            float4 m;
            m.x = -coef * (xs[4*q+0] + cu_d * fu[4*q+0] + cw_d * fw[4*q+0]);
            m.y = -coef * (xs[4*q+1] + cu_d * fu[4*q+1] + cw_d * fw[4*q+1]);
            m.z = -coef * (xs[4*q+2] + cu_d * fu[4*q+2] + cw_d * fw[4*q+2]);
            m.w = -coef * (xs[4*q+3] + cu_d * fu[4*q+3] + cw_d * fw[4*q+3]);
            *(float4*)(hAf + (256 + e) * 32 + ((q ^ sw) << 2)) = m;         // md
        }
    }
    __syncwarp();

    // ---- quad-cooperative scattered RED ----
    {
        int eq = lane >> 2, t = lane & 3;
#pragma unroll
        for (int it = 0; it < 4; it++) {
            int eL = 32 * w + it * 8 + eq;
            if (e0 + eL >= E) continue;
            int s = eis[eL], d = eid[eL];
            int sw = eL & 7;
            float4 m1 = *(const float4*)(hAf + eL * 32 + ((t ^ sw) << 2));
            red_add_v4(&g_acc[(size_t)s * D + 4 * t], m1.x, m1.y, m1.z, m1.w);
            float4 m2 = *(const float4*)(hAf + (256 + eL) * 32 + ((t ^ sw) << 2));
            red_add_v4(&g_acc[(size_t)d * D + 4 * t], m2.x, m2.y, m2.z, m2.w);
        }
    }
}

// out = relu(x - acc), vectorized; restore zero-invariant on g_acc / g_deg
__global__ void out_kernel(const float* __restrict__ x, float* __restrict__ out, int n4) {
    int idx = blockIdx.x * blockDim.x + threadIdx.x;
    if (idx < n4) {
        float4 xv = ((const float4*)x)[idx];
        float4 av = ((const float4*)g_acc)[idx];
        float4 o;
        o.x = fmaxf(xv.x - av.x, 0.0f);
        o.y = fmaxf(xv.y - av.y, 0.0f);
        o.z = fmaxf(xv.z - av.z, 0.0f);
        o.w = fmaxf(xv.w - av.w, 0.0f);
        ((float4*)out)[idx] = o;
        ((float4*)g_acc)[idx] = make_float4(0.f, 0.f, 0.f, 0.f);
    }
    if (idx < N_NODES) g_deg[idx] = 0.0f;
}

extern "C" void kernel_launch(void* const* d_in, const int* in_sizes, int n_in,
                              void* d_out, int out_size) {
    const float* x  = (const float*)d_in[0];
    const int*   ei = (const int*)d_in[1];   // edge_index is int32 (JAX x64 disabled)
    const float* W1 = (const float*)d_in[2];
    const float* b1 = (const float*)d_in[3];
    const float* W2 = (const float*)d_in[4];
    const float* b2 = (const float*)d_in[5];
    float* out = (float*)d_out;

    int E = in_sizes[1] / 2;
    int n = in_sizes[0];
    int n_nodes = n / D;

    size_t smemBytes = (size_t)SMEM_WORDS * 4;   // 72256 B
    cudaFuncSetAttribute(edge_kernel, cudaFuncAttributeMaxDynamicSharedMemorySize,
                         (int)smemBytes);

    deg_kernel<<<(E + 255) / 256, 256>>>(ei, E);
    node_kernel<<<(n_nodes + 255) / 256, 256>>>(x, W1, n_nodes);

    int nTiles = (E + TILE - 1) / TILE;
    edge_kernel<<<nTiles, BLOCK, smemBytes>>>(ei, b1, W2, b2, E);

    int n4 = n / 4;
    out_kernel<<<(n4 + 255) / 256, 256>>>(x, out, n4);
}

// round 17
// speedup vs baseline: 1.0860x; 1.0860x over previous
#include <cuda_runtime.h>
#include <cuda_bf16.h>
#include <cuda_fp16.h>

#define N_NODES 50000
#define D 16
#define H 64
#define RECW 96            // words per node record (384B): P half2[32] Q half2[32] x[16] rsd pad
#define TILE 256
#define BLOCK 256

__device__ float g_acc[N_NODES * D];   // zeroed at module load; out_kernel restores zeros
__device__ float g_deg[N_NODES];
__device__ float g_rec[N_NODES * RECW];

__device__ __forceinline__ void red_add_v4(float* addr, float a, float b, float c, float d) {
    asm volatile("red.global.add.v4.f32 [%0], {%1, %2, %3, %4};"
                 :: "l"(addr), "f"(a), "f"(b), "f"(c), "f"(d) : "memory");
}
__device__ __forceinline__ float relu_(float v) { return fmaxf(v, 0.0f); }
__device__ __forceinline__ unsigned h2_bits(__half2 h) {
    return *reinterpret_cast<unsigned*>(&h);
}
__device__ __forceinline__ float2 h2_to_f2(unsigned raw) {
    __half2 h = *reinterpret_cast<__half2*>(&raw);
    return __half22float2(h);
}
__device__ __forceinline__ void ldmatrix_x4(unsigned& a0, unsigned& a1, unsigned& a2, unsigned& a3,
                                            unsigned addr) {
    asm volatile("ldmatrix.sync.aligned.m8n8.x4.shared.b16 {%0,%1,%2,%3}, [%4];"
                 : "=r"(a0), "=r"(a1), "=r"(a2), "=r"(a3) : "r"(addr));
}
__device__ __forceinline__ void ldmatrix_x2(unsigned& b0, unsigned& b1, unsigned addr) {
    asm volatile("ldmatrix.sync.aligned.m8n8.x2.shared.b16 {%0,%1}, [%2];"
                 : "=r"(b0), "=r"(b1) : "r"(addr));
}
__device__ __forceinline__ void mma_16816(float& c0, float& c1, float& c2, float& c3,
                                          unsigned a0, unsigned a1, unsigned a2, unsigned a3,
                                          unsigned b0, unsigned b1) {
    asm volatile("mma.sync.aligned.m16n8k16.row.col.f32.f16.f16.f32 "
                 "{%0,%1,%2,%3}, {%4,%5,%6,%7}, {%8,%9}, {%0,%1,%2,%3};"
                 : "+f"(c0), "+f"(c1), "+f"(c2), "+f"(c3)
                 : "r"(a0), "r"(a1), "r"(a2), "r"(a3), "r"(b0), "r"(b1));
}

__global__ void deg_kernel(const int* __restrict__ ei, int E) {
    int e = blockIdx.x * blockDim.x + threadIdx.x;
    if (e >= E) return;
    atomicAdd(&g_deg[ei[e]], 1.0f);
    atomicAdd(&g_deg[ei[E + e]], 1.0f);
}

// Per node: P = W1a@x, Q = W1b@x stored half2; x fp32; rsd = 1/sqrt(max(deg,1e-5))
__global__ __launch_bounds__(128)
void node_kernel(const float* __restrict__ x, const float* __restrict__ W1, int n_nodes)
{
    __shared__ float w1s[H * 32];
    for (int i = threadIdx.x; i < H * 32; i += blockDim.x) w1s[i] = W1[i];
    __syncthreads();

    int n = blockIdx.x * blockDim.x + threadIdx.x;
    if (n >= n_nodes) return;

    float xv[D];
    const float4* px = (const float4*)(x + (size_t)n * D);
#pragma unroll
    for (int q = 0; q < 4; q++) {
        float4 v4 = px[q];
        xv[4 * q + 0] = v4.x; xv[4 * q + 1] = v4.y;
        xv[4 * q + 2] = v4.z; xv[4 * q + 3] = v4.w;
    }

    float* rec = &g_rec[(size_t)n * RECW];
    unsigned* recu = (unsigned*)rec;
#pragma unroll 4
    for (int jg = 0; jg < H / 4; jg++) {
        float p[4], qv[4];
#pragma unroll
        for (int jj = 0; jj < 4; jj++) {
            const float* w = &w1s[(jg * 4 + jj) * 32];
            float p0 = 0.f, p1 = 0.f, q0 = 0.f, q1 = 0.f;
#pragma unroll
            for (int k = 0; k < D; k += 2) {
                p0 = fmaf(w[k],          xv[k],     p0);
                p1 = fmaf(w[k + 1],      xv[k + 1], p1);
                q0 = fmaf(w[16 + k],     xv[k],     q0);
                q1 = fmaf(w[16 + k + 1], xv[k + 1], q1);
            }
            p[jj] = p0 + p1;
            qv[jj] = q0 + q1;
        }
        recu[2 * jg + 0]      = h2_bits(__floats2half2_rn(p[0], p[1]));
        recu[2 * jg + 1]      = h2_bits(__floats2half2_rn(p[2], p[3]));
        recu[32 + 2 * jg + 0] = h2_bits(__floats2half2_rn(qv[0], qv[1]));
        recu[32 + 2 * jg + 1] = h2_bits(__floats2half2_rn(qv[2], qv[3]));
    }
#pragma unroll
    for (int q = 0; q < 4; q++)
        *(float4*)(rec + 64 + 4 * q) = px[q];
    rec[80] = rsqrtf(fmaxf(g_deg[n], 1e-5f));
}

// SMEM (u32 words):
//   hA   [512 rows * 32]  rows 0..255 hu / x-s, rows 256..511 hw / x-d (XOR chunk swizzle)
//   w2h  fp16 [16 * 72]   (576 u32)
//   b1f[64], b2s[16], rsdS[256], rsdD[256], eis[256], eid[256]
#define SMEM_WORDS (16384 + 576 + 64 + 16 + 256 + 256 + 256 + 256)

__global__ __launch_bounds__(BLOCK, 3)
void edge_kernel(const int* __restrict__ ei,
                 const float* __restrict__ b1, const float* __restrict__ W2f,
                 const float* __restrict__ b2, int E)
{
    extern __shared__ unsigned smemu[];
    unsigned* hA  = smemu;                         // 16384
    __half*  w2h  = (__half*)(smemu + 16384);      // 576 u32
    float*   b1f  = (float*)(smemu + 16384 + 576); // 64
    float*   b2s  = b1f + 64;                      // 16
    float*   rsdS = b2s + 16;                      // 256
    float*   rsdD = rsdS + 256;                    // 256
    int*     eis  = (int*)(rsdD + 256);            // 256
    int*     eid  = eis + 256;                     // 256
    float*   hAf  = (float*)hA;

    const float* __restrict__ rec = g_rec;

    int tid = threadIdx.x, lane = tid & 31, w = tid >> 5;
    int e0 = blockIdx.x * TILE;

    // ---- init loads ----
    for (int i = tid; i < D * H; i += BLOCK) {       // W2f row-major [16][64]
        int r = i >> 6, c = i & 63;
        w2h[r * 72 + c] = __float2half(W2f[i]);
    }
    if (tid < H) b1f[tid] = b1[tid];
    if (tid < D) b2s[tid] = b2[tid];
    {
        int eg = e0 + tid; if (eg >= E) eg = E - 1;
        eis[tid] = ei[eg];
        eid[tid] = ei[E + eg];
    }
    __syncthreads();

    // ---- phase 1: coalesced fp16 PQ gather -> hu/hw rows (64 half each, swizzled) ----
    {
        int half_ = lane >> 4, cl = lane & 15;
        int sub = cl & 7;                 // 16B chunk (8 hidden units)
        int isHW = cl >> 3;               // 0: hu = P_s+Q_d ; 1: hw = P_d+Q_s
        float bb[8];
#pragma unroll
        for (int k = 0; k < 8; k++) bb[k] = b1f[8 * sub + k];
#pragma unroll 4
        for (int it = 0; it < TILE / 16; it++) {
            int eL = it * 16 + (w << 1) + half_;
            int s = eis[eL], d = eid[eL];
            const unsigned* rn1 = (const unsigned*)(rec + (size_t)(isHW ? d : s) * RECW);
            const unsigned* rn2 = (const unsigned*)(rec + (size_t)(isHW ? s : d) * RECW);
            uint4 v1 = *(const uint4*)(rn1 + 4 * sub);        // P piece (8 half)
            uint4 v2 = *(const uint4*)(rn2 + 32 + 4 * sub);   // Q piece (8 half)
            uint4 o;
            { float2 a = h2_to_f2(v1.x), b = h2_to_f2(v2.x);
              o.x = h2_bits(__floats2half2_rn(relu_(a.x + b.x + bb[0]), relu_(a.y + b.y + bb[1]))); }
            { float2 a = h2_to_f2(v1.y), b = h2_to_f2(v2.y);
              o.y = h2_bits(__floats2half2_rn(relu_(a.x + b.x + bb[2]), relu_(a.y + b.y + bb[3]))); }
            { float2 a = h2_to_f2(v1.z), b = h2_to_f2(v2.z);
              o.z = h2_bits(__floats2half2_rn(relu_(a.x + b.x + bb[4]), relu_(a.y + b.y + bb[5]))); }
            { float2 a = h2_to_f2(v1.w), b = h2_to_f2(v2.w);
              o.w = h2_bits(__floats2half2_rn(relu_(a.x + b.x + bb[6]), relu_(a.y + b.y + bb[7]))); }
            int row = isHW ? (256 + eL) : eL;
            *(uint4*)(hA + row * 32 + ((sub ^ (row & 7)) << 2)) = o;
        }
    }
    __syncthreads();

    // ---- MMA phase (warp-local: warp w owns edges [32w, 32w+32)) ----
    unsigned hbase = (unsigned)__cvta_generic_to_shared(hA);
    unsigned wbase = (unsigned)__cvta_generic_to_shared(w2h);

    unsigned bf[2][4][2];
    {
        int l15 = lane & 15;
#pragma unroll
        for (int n = 0; n < 2; n++)
#pragma unroll
            for (int kt = 0; kt < 4; kt++) {
                unsigned addr = wbase + (8 * n + (l15 & 7)) * 144 + kt * 32 + ((l15 >> 3) << 4);
                ldmatrix_x2(bf[n][kt][0], bf[n][kt][1], addr);
            }
    }

    int rl = lane >> 2, cc = 2 * (lane & 3);
#pragma unroll
    for (int m = 0; m < 4; m++) {
        int rowbase = (m < 2) ? (32 * w + 16 * m) : (256 + 32 * w + 16 * (m - 2));
        float c0[4] = {0.f, 0.f, 0.f, 0.f};
        float c1[4] = {0.f, 0.f, 0.f, 0.f};
#pragma unroll
        for (int kt = 0; kt < 4; kt++) {
            int r = rowbase + (lane & 15);
            unsigned chunk = 2 * kt + (lane >> 4);
            unsigned addr = hbase + r * 128 + ((chunk ^ (unsigned)(r & 7)) << 4);
            unsigned a0, a1, a2, a3;
            ldmatrix_x4(a0, a1, a2, a3, addr);
            mma_16816(c0[0], c0[1], c0[2], c0[3], a0, a1, a2, a3, bf[0][kt][0], bf[0][kt][1]);
            mma_16816(c1[0], c1[1], c1[2], c1[3], a0, a1, a2, a3, bf[1][kt][0], bf[1][kt][1]);
        }
        // D -> smem rows, chunks 0..3 (fu / fw, 16 fp32)
#pragma unroll
        for (int hh = 0; hh < 2; hh++) {
            int R = rowbase + rl + 8 * hh;
            int sw = R & 7;
            {
                int fidx = cc;                       // n=0 cols 0..7
                float* p = hAf + R * 32 + (((fidx >> 2) ^ sw) << 2) + (fidx & 3);
                *(float2*)p = make_float2(hh ? c0[2] : c0[0], hh ? c0[3] : c0[1]);
            }
            {
                int fidx = 8 + cc;                   // n=1 cols 8..15
                float* p = hAf + R * 32 + (((fidx >> 2) ^ sw) << 2) + (fidx & 3);
                *(float2*)p = make_float2(hh ? c1[2] : c1[0], hh ? c1[3] : c1[1]);
            }
        }
    }

    // ---- x + rsd staging (warp-local, quad-cooperative) into chunks 4..7 ----
    {
        int eq = lane >> 2, t = lane & 3;
#pragma unroll
        for (int it = 0; it < 4; it++) {
            int eL = 32 * w + it * 8 + eq;
            int s = eis[eL], d = eid[eL];
            const float* rs = rec + (size_t)s * RECW;
            const float* rd = rec + (size_t)d * RECW;
            float4 a = *(const float4*)(rs + 64 + 4 * t);
            float4 b = *(const float4*)(rd + 64 + 4 * t);
            int Ru = eL, Rw = 256 + eL;
            int ch = 4 + t;
            *(float4*)(hAf + Ru * 32 + ((ch ^ (Ru & 7)) << 2)) = a;   // xs
            *(float4*)(hAf + Rw * 32 + ((ch ^ (Rw & 7)) << 2)) = b;   // xd
            if (t == 0) rsdS[eL] = rs[80];
            if (t == 1) rsdD[eL] = rd[80];
        }
    }
    __syncwarp();

    // ---- epilogue: thread-per-edge dots + messages (all reads warp-local) ----
    {
        int e = tid;
        int sw = e & 7;
        float fu[16], fw[16], xs[16], xd[16];
#pragma unroll
        for (int q = 0; q < 4; q++) {
            float4 a  = *(const float4*)(hAf + e * 32 + ((q ^ sw) << 2));
            float4 xA = *(const float4*)(hAf + e * 32 + (((q + 4) ^ sw) << 2));
            float4 b  = *(const float4*)(hAf + (256 + e) * 32 + ((q ^ sw) << 2));
            float4 xB = *(const float4*)(hAf + (256 + e) * 32 + (((q + 4) ^ sw) << 2));
            fu[4*q+0] = a.x;  fu[4*q+1] = a.y;  fu[4*q+2] = a.z;  fu[4*q+3] = a.w;
            xs[4*q+0] = xA.x; xs[4*q+1] = xA.y; xs[4*q+2] = xA.z; xs[4*q+3] = xA.w;
            fw[4*q+0] = b.x;  fw[4*q+1] = b.y;  fw[4*q+2] = b.z;  fw[4*q+3] = b.w;
            xd[4*q+0] = xB.x; xd[4*q+1] = xB.y; xd[4*q+2] = xB.z; xd[4*q+3] = xB.w;
        }
#pragma unroll
        for (int i = 0; i < 16; i++) {
            float b2i = b2s[i];
            fu[i] += b2i;
            fw[i] += b2i;
        }
        float coef = rsdS[e] * rsdD[e];

        float n2u = 0.f, n2w = 0.f, puw = 0.f, pu_xd = 0.f, pw_xd = 0.f, pu_xs = 0.f, pw_xs = 0.f;
#pragma unroll
        for (int i = 0; i < 16; i++) {
            n2u   = fmaf(fu[i], fu[i], n2u);
            n2w   = fmaf(fw[i], fw[i], n2w);
            puw   = fmaf(fu[i], fw[i], puw);
            pu_xd = fmaf(fu[i], xd[i], pu_xd);
            pw_xd = fmaf(fw[i], xd[i], pw_xd);
            pu_xs = fmaf(fu[i], xs[i], pu_xs);
            pw_xs = fmaf(fw[i], xs[i], pw_xs);
        }
        float invu = 1.0f / fmaxf(sqrtf(n2u), 1e-12f);
        float invw = 1.0f / fmaxf(sqrtf(n2w), 1e-12f);
        float uw   = puw   * invu * invw;
        float u_xd = pu_xd * invu;
        float w_xd = pw_xd * invw;
        float u_xs = pu_xs * invu;
        float w_xs = pw_xs * invw;

        // F_s = I-2uu^T, F_d = I-2ww^T, L = -F_s^T F_d ; coefficients act on raw fu/fw
        float cu_s = (-2.0f * u_xd + 4.0f * uw * w_xd) * invu;
        float cw_s = (-2.0f * w_xd) * invw;
        float cu_d = (-2.0f * u_xs) * invu;
        float cw_d = (-2.0f * w_xs + 4.0f * uw * u_xs) * invw;

#pragma unroll
        for (int q = 0; q < 4; q++) {
            float4 m;
            m.x = -coef * (xd[4*q+0] + cu_s * fu[4*q+0] + cw_s * fw[4*q+0]);
            m.y = -coef * (xd[4*q+1] + cu_s * fu[4*q+1] + cw_s * fw[4*q+1]);
            m.z = -coef * (xd[4*q+2] + cu_s * fu[4*q+2] + cw_s * fw[4*q+2]);
            m.w = -coef * (xd[4*q+3] + cu_s * fu[4*q+3] + cw_s * fw[4*q+3]);
            *(float4*)(hAf + e * 32 + ((q ^ sw) << 2)) = m;                 // ms
        }
#pragma unroll
        for (int q = 0; q < 4; q++) {
            float4 m;
            m.x = -coef * (xs[4*q+0] + cu_d * fu[4*q+0] + cw_d * fw[4*q+0]);
            m.y = -coef * (xs[4*q+1] + cu_d * fu[4*q+1] + cw_d * fw[4*q+1]);
            m.z = -coef * (xs[4*q+2] + cu_d * fu[4*q+2] + cw_d * fw[4*q+2]);
            m.w = -coef * (xs[4*q+3] + cu_d * fu[4*q+3] + cw_d * fw[4*q+3]);
            *(float4*)(hAf + (256 + e) * 32 + ((q ^ sw) << 2)) = m;         // md
        }
    }
    __syncwarp();

    // ---- quad-cooperative scattered RED ----
    {
        int eq = lane >> 2, t = lane & 3;
#pragma unroll
        for (int it = 0; it < 4; it++) {
            int eL = 32 * w + it * 8 + eq;
            if (e0 + eL >= E) continue;
            int s = eis[eL], d = eid[eL];
            int sw = eL & 7;
            float4 m1 = *(const float4*)(hAf + eL * 32 + ((t ^ sw) << 2));
            red_add_v4(&g_acc[(size_t)s * D + 4 * t], m1.x, m1.y, m1.z, m1.w);
            float4 m2 = *(const float4*)(hAf + (256 + eL) * 32 + ((t ^ sw) << 2));
            red_add_v4(&g_acc[(size_t)d * D + 4 * t], m2.x, m2.y, m2.z, m2.w);
        }
    }
}

// out = relu(x - acc), vectorized; restore zero-invariant on g_acc / g_deg
__global__ void out_kernel(const float* __restrict__ x, float* __restrict__ out, int n4) {
    int idx = blockIdx.x * blockDim.x + threadIdx.x;
    if (idx < n4) {
        float4 xv = ((const float4*)x)[idx];
        float4 av = ((const float4*)g_acc)[idx];
        float4 o;
        o.x = fmaxf(xv.x - av.x, 0.0f);
        o.y = fmaxf(xv.y - av.y, 0.0f);
        o.z = fmaxf(xv.z - av.z, 0.0f);
        o.w = fmaxf(xv.w - av.w, 0.0f);
        ((float4*)out)[idx] = o;
        ((float4*)g_acc)[idx] = make_float4(0.f, 0.f, 0.f, 0.f);
    }
    if (idx < N_NODES) g_deg[idx] = 0.0f;
}

extern "C" void kernel_launch(void* const* d_in, const int* in_sizes, int n_in,
                              void* d_out, int out_size) {
    const float* x  = (const float*)d_in[0];
    const int*   ei = (const int*)d_in[1];   // edge_index is int32 (JAX x64 disabled)
    const float* W1 = (const float*)d_in[2];
    const float* b1 = (const float*)d_in[3];
    const float* W2 = (const float*)d_in[4];
    const float* b2 = (const float*)d_in[5];
    float* out = (float*)d_out;

    int E = in_sizes[1] / 2;
    int n = in_sizes[0];
    int n_nodes = n / D;

    size_t smemBytes = (size_t)SMEM_WORDS * 4;   // 72256 B
    cudaFuncSetAttribute(edge_kernel, cudaFuncAttributeMaxDynamicSharedMemorySize,
                         (int)smemBytes);

    deg_kernel<<<(E + 255) / 256, 256>>>(ei, E);
    node_kernel<<<(n_nodes + 127) / 128, 128>>>(x, W1, n_nodes);

    int nTiles = (E + TILE - 1) / TILE;
    edge_kernel<<<nTiles, BLOCK, smemBytes>>>(ei, b1, W2, b2, E);

    int n4 = n / 4;
    out_kernel<<<(n4 + 255) / 256, 256>>>(x, out, n4);
}